// round 15
// baseline (speedup 1.0000x reference)
#include <cuda_runtime.h>
#include <cstdint>

#define HW      49
#define CDIM    256
#define NTHR    256
#define NB      2              // batches per CTA
#define GRID    1024
#define NSUB    16             // 16-channel sub-chunks
#define BUFW    4096           // words per sub-buffer: 2 batches * 2048
#define WM_BYTE 65536          // u8 mask after 4 sub-buffers
#define SN_OFF  16992          // norm words (67968/4 rounded to 16992)
#define DYN_WORDS (SN_OFF + 256)
#define NPAIR   1568           // channel-pairs per sub-chunk (2b*2t*8kp*49)

// pack two fp32 -> bf16x2: lower 16 = even channel, upper 16 = odd channel
__device__ __forceinline__ uint32_t bf16pack(float even, float odd) {
    uint32_t r;
    asm("cvt.rn.bf16x2.f32 %0, %1, %2;" : "=r"(r) : "f"(odd), "f"(even));
    return r;
}
__device__ __forceinline__ void mma16(float* d, const uint32_t* a,
                                      uint32_t b0, uint32_t b1) {
    asm("mma.sync.aligned.m16n8k16.row.col.f32.bf16.bf16.f32 "
        "{%0,%1,%2,%3}, {%4,%5,%6,%7}, {%8,%9}, {%0,%1,%2,%3};"
        : "+f"(d[0]), "+f"(d[1]), "+f"(d[2]), "+f"(d[3])
        : "r"(a[0]), "r"(a[1]), "r"(a[2]), "r"(a[3]), "r"(b0), "r"(b1));
}

__global__ __launch_bounds__(NTHR, 3) void pixpro_q4(
    const float* __restrict__ baseF,   // [B, 256, 49]
    const float* __restrict__ momF,    // [B, 256, 49]
    const int*   __restrict__ baseA,   // [49*49] (p*49+q)
    const int*   __restrict__ momA,    // [49*49]
    float*       __restrict__ out)     // [B]
{
    extern __shared__ float sm[];
    uint32_t* smw = (uint32_t*)sm;
    unsigned char* wmb = (unsigned char*)sm + WM_BYTE;
    __shared__ float wsum[8];

    const int tid  = threadIdx.x;
    const int wid  = tid >> 5;
    const int lane = tid & 31;
    const int tg   = lane & 3;
    const int gq   = lane >> 2;
    const int b0   = blockIdx.x * NB;

    // ---- init mask (u8) + norm accumulators ----
    for (int i = tid; i < HW * HW; i += NTHR) {
        int p = i / HW, q = i - p * HW;
        wmb[i] = (unsigned char)((baseA[i] == 1) + (momA[q * HW + p] == 1));
    }
    sm[SN_OFF + tid] = 0.f;

    // ---- staging descriptors ----
    uint32_t off[7], dst[7];
    float accn[7];
    #pragma unroll
    for (int j = 0; j < 7; ++j) {
        accn[j] = 0.f;
        int e = tid + j * NTHR;
        if (e < NPAIR) {
            int bb  = e / 784;
            int r   = e - bb * 784;
            int t   = r / 392;
            int s   = r - t * 392;
            int kp  = s / 49;
            int pos = s - kp * 49;
            off[j] = (uint32_t)((b0 + bb) * (CDIM * HW) + kp * 98 + pos)
                   | (t ? 0x80000000u : 0u);
            dst[j] = (uint32_t)(bb * 2048 + (t ? 1152 + kp * 56 : kp * 72) + pos);
        }
    }

    auto ldg_chunk = [&](float* v0, float* v1, int cc) {
        #pragma unroll
        for (int j = 0; j < 7; ++j)
            if (j < 6 || tid < (NPAIR - 6 * NTHR)) {
                uint32_t o = off[j];
                const float* sp = (o & 0x80000000u) ? momF : baseF;
                const float* p  = sp + (o & 0x7FFFFFFFu) + cc * 784;
                v0[j] = __ldg(p); v1[j] = __ldg(p + 49);
            }
    };
    auto sts_chunk = [&](const float* v0, const float* v1, int bw) {
        uint32_t* dbuf = smw + bw * BUFW;
        #pragma unroll
        for (int j = 0; j < 7; ++j)
            if (j < 6 || tid < (NPAIR - 6 * NTHR)) {
                uint32_t hi = bf16pack(v0[j], v1[j]);
                float h0 = __uint_as_float(hi << 16);
                float h1 = __uint_as_float(hi & 0xFFFF0000u);
                uint32_t mo = (off[j] & 0x80000000u) ? 448u : 576u;
                dbuf[dst[j]]      = hi;
                dbuf[dst[j] + mo] = bf16pack(v0[j] - h0, v1[j] - h1);
                accn[j] = fmaf(v0[j], v0[j], fmaf(v1[j], v1[j], accn[j]));
            }
    };

    // ---- MMA state: round-8 proven m16 layout ----
    const int bb = wid >> 2;
    const int mr = (wid & 3) * 16 + gq;
    float acc[7][4];
    #pragma unroll
    for (int nt = 0; nt < 7; ++nt)
        #pragma unroll
        for (int u = 0; u < 4; ++u) acc[nt][u] = 0.f;

    auto mma_chunk = [&](int bw) {
        const uint32_t* W  = smw + bw * BUFW + bb * 2048;
        const uint32_t* Bh = W + 1152;
        uint32_t ah[4], am[4];
        ah[0] = W[tg * 72 + mr];
        ah[1] = W[tg * 72 + mr + 8];
        ah[2] = W[(tg + 4) * 72 + mr];
        ah[3] = W[(tg + 4) * 72 + mr + 8];
        am[0] = W[576 + tg * 72 + mr];
        am[1] = W[576 + tg * 72 + mr + 8];
        am[2] = W[576 + (tg + 4) * 72 + mr];
        am[3] = W[576 + (tg + 4) * 72 + mr + 8];
        #pragma unroll
        for (int nt = 0; nt < 7; ++nt) {
            int o = tg * 56 + nt * 8 + gq;
            uint32_t bh0 = Bh[o],       bh1 = Bh[o + 224];
            uint32_t bm0 = Bh[o + 448], bm1 = Bh[o + 672];
            mma16(acc[nt], ah, bh0, bh1);   // hi * hi
            mma16(acc[nt], ah, bm0, bm1);   // hi * mid
            mma16(acc[nt], am, bh0, bh1);   // mid * hi
        }
    };

    // ---- prologue: sub-chunks 0,1 staged; 2 prefetched ----
    float v0[7], v1[7];
    ldg_chunk(v0, v1, 0);
    sts_chunk(v0, v1, 0);
    ldg_chunk(v0, v1, 1);
    sts_chunk(v0, v1, 1);
    ldg_chunk(v0, v1, 2);

    // ---- main loop: ONE barrier per 2 sub-chunks (8 total), 4 sub-buffers ----
    for (int i = 0; i < 8; ++i) {
        const int c = 2 * i;
        __syncthreads();                            // S[c&3], S[(c+1)&3] ready
        if (c + 2 < NSUB) sts_chunk(v0, v1, (c + 2) & 3);
        if (c + 3 < NSUB) ldg_chunk(v0, v1, c + 3);
        mma_chunk(c & 3);
        if (c + 3 < NSUB) sts_chunk(v0, v1, (c + 3) & 3);
        if (c + 4 < NSUB) ldg_chunk(v0, v1, c + 4);
        mma_chunk((c + 1) & 3);
    }

    // ---- flush norm partials ----
    #pragma unroll
    for (int j = 0; j < 7; ++j) {
        int e = tid + j * NTHR;
        if (e < NPAIR) {
            int bbx = e / 784;
            int r   = e - bbx * 784;
            int t   = r / 392;
            int pos = (r - t * 392) % 49;
            atomicAdd(&sm[SN_OFF + (bbx * 2 + t) * 64 + pos], accn[j]);
        }
    }
    __syncthreads();
    sm[SN_OFF + tid] = rsqrtf(sm[SN_OFF + tid]);
    __syncthreads();

    // ---- epilogue: mask + norms + reduce ----
    {
        const float* invP = sm + SN_OFF + (bb * 2 + 0) * 64;  // base norms
        const float* invQ = sm + SN_OFF + (bb * 2 + 1) * 64;  // moment norms
        const int r0 = mr;
        const int r1 = r0 + 8;
        const int c0 = tg * 2;
        const bool u0 = r0 < HW, u1 = r1 < HW;
        const float ip0 = u0 ? invP[r0] : 0.f;
        const float ip1 = u1 ? invP[r1] : 0.f;
        float part = 0.f;
        #pragma unroll
        for (int nt = 0; nt < 7; ++nt) {
            int q0 = nt * 8 + c0;
            int q1 = q0 + 1;
            if (q0 < HW) {
                float iq = invQ[q0];
                if (u0) part = fmaf(acc[nt][0], (float)wmb[r0 * HW + q0] * ip0 * iq, part);
                if (u1) part = fmaf(acc[nt][2], (float)wmb[r1 * HW + q0] * ip1 * iq, part);
            }
            if (q1 < HW) {
                float iq = invQ[q1];
                if (u0) part = fmaf(acc[nt][1], (float)wmb[r0 * HW + q1] * ip0 * iq, part);
                if (u1) part = fmaf(acc[nt][3], (float)wmb[r1 * HW + q1] * ip1 * iq, part);
            }
        }
        #pragma unroll
        for (int o = 16; o; o >>= 1) part += __shfl_xor_sync(0xFFFFFFFFu, part, o);
        if (lane == 0) wsum[wid] = part;
    }
    __syncthreads();
    if (tid < NB) {
        float t = wsum[tid * 4] + wsum[tid * 4 + 1]
                + wsum[tid * 4 + 2] + wsum[tid * 4 + 3];
        out[b0 + tid] = -t * (1.0f / 2401.0f);
    }
}

extern "C" void kernel_launch(void* const* d_in, const int* in_sizes, int n_in,
                              void* d_out, int out_size) {
    const float* baseF = (const float*)d_in[0];
    const float* momF  = (const float*)d_in[1];
    const int*   baseA = (const int*)d_in[2];
    const int*   momA  = (const int*)d_in[3];
    float* out = (float*)d_out;
    (void)in_sizes; (void)n_in; (void)out_size;

    const int dynBytes = DYN_WORDS * 4;
    cudaFuncSetAttribute(pixpro_q4, cudaFuncAttributeMaxDynamicSharedMemorySize, dynBytes);
    pixpro_q4<<<GRID, NTHR, dynBytes>>>(baseF, momF, baseA, momA, out);
}

// round 16
// speedup vs baseline: 1.2502x; 1.2502x over previous
#include <cuda_runtime.h>
#include <cstdint>

#define HW      49
#define CDIM    256
#define NTHR    256
#define NB      2              // batches per CTA
#define GRID    1024
#define NCHUNK  16             // 16 channels per chunk
#define BUFW    4096           // words per buffer: 2 batches * 2048
#define WM_OFF  16384          // after 4 buffers; combined mask (float), 2401 (pad 2432)
#define SN_OFF  (WM_OFF + 2432)
#define DYN_WORDS (SN_OFF + 256)
#define NPAIR   1568           // channel-pairs per chunk (2b*2t*8kp*49)

// pack two fp32 -> bf16x2: lower 16 = even channel, upper 16 = odd channel
__device__ __forceinline__ uint32_t bf16pack(float even, float odd) {
    uint32_t r;
    asm("cvt.rn.bf16x2.f32 %0, %1, %2;" : "=r"(r) : "f"(odd), "f"(even));
    return r;
}
__device__ __forceinline__ void mma16(float* d, const uint32_t* a,
                                      uint32_t b0, uint32_t b1) {
    asm("mma.sync.aligned.m16n8k16.row.col.f32.bf16.bf16.f32 "
        "{%0,%1,%2,%3}, {%4,%5,%6,%7}, {%8,%9}, {%0,%1,%2,%3};"
        : "+f"(d[0]), "+f"(d[1]), "+f"(d[2]), "+f"(d[3])
        : "r"(a[0]), "r"(a[1]), "r"(a[2]), "r"(a[3]), "r"(b0), "r"(b1));
}

__global__ __launch_bounds__(NTHR, 2) void pixpro_b4(
    const float* __restrict__ baseF,   // [B, 256, 49]
    const float* __restrict__ momF,    // [B, 256, 49]
    const int*   __restrict__ baseA,   // [49*49] (p*49+q)
    const int*   __restrict__ momA,    // [49*49]
    float*       __restrict__ out)     // [B]
{
    extern __shared__ float sm[];
    uint32_t* smw = (uint32_t*)sm;
    __shared__ float wsum[8];

    const int tid  = threadIdx.x;
    const int wid  = tid >> 5;
    const int lane = tid & 31;
    const int tg   = lane & 3;
    const int gq   = lane >> 2;
    const int b0   = blockIdx.x * NB;

    // ---- init mask + norm accumulators ----
    for (int i = tid; i < HW * HW; i += NTHR) {
        int p = i / HW, q = i - p * HW;
        sm[WM_OFF + i] = (float)((baseA[i] == 1) + (momA[q * HW + p] == 1));
    }
    sm[SN_OFF + tid] = 0.f;

    // ---- staging descriptors: off (gmem word, t in sign bit) + dst (smem word) ----
    uint32_t off[7], dst[7];
    float accn[7];
    #pragma unroll
    for (int j = 0; j < 7; ++j) {
        accn[j] = 0.f;
        int e = tid + j * NTHR;
        if (e < NPAIR) {
            int bb  = e / 784;
            int r   = e - bb * 784;
            int t   = r / 392;
            int s   = r - t * 392;
            int kp  = s / 49;
            int pos = s - kp * 49;
            off[j] = (uint32_t)((b0 + bb) * (CDIM * HW) + kp * 98 + pos)
                   | (t ? 0x80000000u : 0u);
            dst[j] = (uint32_t)(bb * 2048 + (t ? 1152 + kp * 56 : kp * 72) + pos);
        }
    }

    auto ldg_chunk = [&](float* v0, float* v1, int cc) {
        #pragma unroll
        for (int j = 0; j < 7; ++j)
            if (j < 6 || tid < (NPAIR - 6 * NTHR)) {
                uint32_t o = off[j];
                const float* sp = (o & 0x80000000u) ? momF : baseF;
                const float* p  = sp + (o & 0x7FFFFFFFu) + cc * 784;
                v0[j] = __ldg(p); v1[j] = __ldg(p + 49);
            }
    };
    auto sts_chunk = [&](const float* v0, const float* v1, int bw) {
        uint32_t* dbuf = smw + bw * BUFW;
        #pragma unroll
        for (int j = 0; j < 7; ++j)
            if (j < 6 || tid < (NPAIR - 6 * NTHR)) {
                uint32_t hi = bf16pack(v0[j], v1[j]);
                float h0 = __uint_as_float(hi << 16);
                float h1 = __uint_as_float(hi & 0xFFFF0000u);
                uint32_t mo = (off[j] & 0x80000000u) ? 448u : 576u;
                dbuf[dst[j]]      = hi;
                dbuf[dst[j] + mo] = bf16pack(v0[j] - h0, v1[j] - h1);
                accn[j] = fmaf(v0[j], v0[j], fmaf(v1[j], v1[j], accn[j]));
            }
    };

    // ---- MMA state (round-8 proven m16 layout) ----
    const int bb = wid >> 2;
    const int mr = (wid & 3) * 16 + gq;
    float acc[7][4];
    #pragma unroll
    for (int nt = 0; nt < 7; ++nt)
        #pragma unroll
        for (int u = 0; u < 4; ++u) acc[nt][u] = 0.f;

    auto mma_chunk = [&](int bw) {
        const uint32_t* W  = smw + bw * BUFW + bb * 2048;
        const uint32_t* Bh = W + 1152;
        uint32_t ah[4], am[4];
        ah[0] = W[tg * 72 + mr];
        ah[1] = W[tg * 72 + mr + 8];
        ah[2] = W[(tg + 4) * 72 + mr];
        ah[3] = W[(tg + 4) * 72 + mr + 8];
        am[0] = W[576 + tg * 72 + mr];
        am[1] = W[576 + tg * 72 + mr + 8];
        am[2] = W[576 + (tg + 4) * 72 + mr];
        am[3] = W[576 + (tg + 4) * 72 + mr + 8];
        #pragma unroll
        for (int nt = 0; nt < 7; ++nt) {
            int o = tg * 56 + nt * 8 + gq;
            uint32_t bh0 = Bh[o],       bh1 = Bh[o + 224];
            uint32_t bm0 = Bh[o + 448], bm1 = Bh[o + 672];
            mma16(acc[nt], ah, bh0, bh1);   // hi * hi
            mma16(acc[nt], ah, bm0, bm1);   // hi * mid
            mma16(acc[nt], am, bh0, bh1);   // mid * hi
        }
    };

    // ---- prologue: chunks 0,1 staged; 2,3 prefetched (two register sets) ----
    float va0[7], va1[7], vb0[7], vb1[7];
    ldg_chunk(va0, va1, 0);
    sts_chunk(va0, va1, 0);
    ldg_chunk(vb0, vb1, 1);
    sts_chunk(vb0, vb1, 1);
    ldg_chunk(va0, va1, 2);
    ldg_chunk(vb0, vb1, 3);

    // ---- main loop: ONE barrier per 2 chunks (8 total), 4 buffers ----
    // interval i (c = 2i): bufs c&3,(c+1)&3 ready; va holds chunk c+2, vb c+3.
    // STS targets (c+2)&3,(c+3)&3 — disjoint from MMA's c&3,(c+1)&3 mod 4.
    for (int c = 0; c < NCHUNK; c += 2) {
        __syncthreads();
        if (c + 2 < NCHUNK) {
            sts_chunk(va0, va1, (c + 2) & 3);
            if (c + 4 < NCHUNK) ldg_chunk(va0, va1, c + 4);
        }
        if (c + 3 < NCHUNK) {
            sts_chunk(vb0, vb1, (c + 3) & 3);
            if (c + 5 < NCHUNK) ldg_chunk(vb0, vb1, c + 5);
        }
        mma_chunk(c & 3);
        mma_chunk((c + 1) & 3);
    }

    // ---- flush norm partials ----
    #pragma unroll
    for (int j = 0; j < 7; ++j) {
        int e = tid + j * NTHR;
        if (e < NPAIR) {
            int bbx = e / 784;
            int r   = e - bbx * 784;
            int t   = r / 392;
            int pos = (r - t * 392) % 49;
            atomicAdd(&sm[SN_OFF + (bbx * 2 + t) * 64 + pos], accn[j]);
        }
    }
    __syncthreads();
    sm[SN_OFF + tid] = rsqrtf(sm[SN_OFF + tid]);
    __syncthreads();

    // ---- epilogue: mask + norms + reduce ----
    {
        const float* invP = sm + SN_OFF + (bb * 2 + 0) * 64;  // base norms
        const float* invQ = sm + SN_OFF + (bb * 2 + 1) * 64;  // moment norms
        const float* wm   = sm + WM_OFF;
        const int r0 = mr;
        const int r1 = r0 + 8;
        const int c0 = tg * 2;
        const bool u0 = r0 < HW, u1 = r1 < HW;
        const float ip0 = u0 ? invP[r0] : 0.f;
        const float ip1 = u1 ? invP[r1] : 0.f;
        float part = 0.f;
        #pragma unroll
        for (int nt = 0; nt < 7; ++nt) {
            int q0 = nt * 8 + c0;
            int q1 = q0 + 1;
            if (q0 < HW) {
                float iq = invQ[q0];
                if (u0) part = fmaf(acc[nt][0], wm[r0 * HW + q0] * ip0 * iq, part);
                if (u1) part = fmaf(acc[nt][2], wm[r1 * HW + q0] * ip1 * iq, part);
            }
            if (q1 < HW) {
                float iq = invQ[q1];
                if (u0) part = fmaf(acc[nt][1], wm[r0 * HW + q1] * ip0 * iq, part);
                if (u1) part = fmaf(acc[nt][3], wm[r1 * HW + q1] * ip1 * iq, part);
            }
        }
        #pragma unroll
        for (int o = 16; o; o >>= 1) part += __shfl_xor_sync(0xFFFFFFFFu, part, o);
        if (lane == 0) wsum[wid] = part;
    }
    __syncthreads();
    if (tid < NB) {
        float t = wsum[tid * 4] + wsum[tid * 4 + 1]
                + wsum[tid * 4 + 2] + wsum[tid * 4 + 3];
        out[b0 + tid] = -t * (1.0f / 2401.0f);
    }
}

extern "C" void kernel_launch(void* const* d_in, const int* in_sizes, int n_in,
                              void* d_out, int out_size) {
    const float* baseF = (const float*)d_in[0];
    const float* momF  = (const float*)d_in[1];
    const int*   baseA = (const int*)d_in[2];
    const int*   momA  = (const int*)d_in[3];
    float* out = (float*)d_out;
    (void)in_sizes; (void)n_in; (void)out_size;

    const int dynBytes = DYN_WORDS * 4;
    cudaFuncSetAttribute(pixpro_b4, cudaFuncAttributeMaxDynamicSharedMemorySize, dynBytes);
    pixpro_b4<<<GRID, NTHR, dynBytes>>>(baseF, momF, baseA, momA, out);
}

// round 17
// speedup vs baseline: 1.3881x; 1.1103x over previous
#include <cuda_runtime.h>
#include <cstdint>

#define HW      49
#define CDIM    256
#define NTHR    256
#define NB      2              // batches per CTA
#define GRID    1024
#define NCHUNK  16             // 16 channels per chunk
#define BBLK    1600           // words per batch block: A hi 576 + A lo 576 + B hi 448
#define BUFW    3200           // words per buffer (2 batches)
#define WM_OFF  6400           // combined mask (float), 2401 (pad 2432)
#define SN_OFF  (WM_OFF + 2432)
#define DYN_WORDS (SN_OFF + 256)
#define NPAIR   1568           // channel-pairs per chunk (2b*2t*8kp*49)

// pack two fp32 -> f16x2: lower 16 = even channel, upper 16 = odd channel
__device__ __forceinline__ uint32_t f16pack(float even, float odd) {
    uint32_t r;
    asm("cvt.rn.f16x2.f32 %0, %1, %2;" : "=r"(r) : "f"(odd), "f"(even));
    return r;
}
__device__ __forceinline__ void f16unpack(uint32_t w, float& lo, float& hi) {
    asm("{\n\t.reg .b16 l, h;\n\t"
        "mov.b32 {l, h}, %2;\n\t"
        "cvt.f32.f16 %0, l;\n\t"
        "cvt.f32.f16 %1, h;\n\t}"
        : "=f"(lo), "=f"(hi) : "r"(w));
}
__device__ __forceinline__ void mma16f(float* d, const uint32_t* a,
                                       uint32_t b0, uint32_t b1) {
    asm("mma.sync.aligned.m16n8k16.row.col.f32.f16.f16.f32 "
        "{%0,%1,%2,%3}, {%4,%5,%6,%7}, {%8,%9}, {%0,%1,%2,%3};"
        : "+f"(d[0]), "+f"(d[1]), "+f"(d[2]), "+f"(d[3])
        : "r"(a[0]), "r"(a[1]), "r"(a[2]), "r"(a[3]), "r"(b0), "r"(b1));
}

__global__ __launch_bounds__(NTHR, 2) void pixpro_f16(
    const float* __restrict__ baseF,   // [B, 256, 49]
    const float* __restrict__ momF,    // [B, 256, 49]
    const int*   __restrict__ baseA,   // [49*49] (p*49+q)
    const int*   __restrict__ momA,    // [49*49]
    float*       __restrict__ out)     // [B]
{
    extern __shared__ float sm[];
    uint32_t* smw = (uint32_t*)sm;
    __shared__ float wsum[8];

    const int tid  = threadIdx.x;
    const int wid  = tid >> 5;
    const int lane = tid & 31;
    const int tg   = lane & 3;
    const int gq   = lane >> 2;
    const int b0   = blockIdx.x * NB;

    // ---- init mask + norm accumulators ----
    for (int i = tid; i < HW * HW; i += NTHR) {
        int p = i / HW, q = i - p * HW;
        sm[WM_OFF + i] = (float)((baseA[i] == 1) + (momA[q * HW + p] == 1));
    }
    sm[SN_OFF + tid] = 0.f;

    // ---- staging descriptors: off (gmem word, B-side in sign bit) + dst ----
    uint32_t off[7], dst[7];
    float accn[7];
    #pragma unroll
    for (int j = 0; j < 7; ++j) {
        accn[j] = 0.f;
        int e = tid + j * NTHR;
        if (e < NPAIR) {
            int bb  = e / 784;
            int r   = e - bb * 784;
            int t   = r / 392;                 // 0 = base(A), 1 = moment(B)
            int s   = r - t * 392;
            int kp  = s / 49;
            int pos = s - kp * 49;
            off[j] = (uint32_t)((b0 + bb) * (CDIM * HW) + kp * 98 + pos)
                   | (t ? 0x80000000u : 0u);
            dst[j] = (uint32_t)(bb * BBLK + (t ? 1152 + kp * 56 : kp * 72) + pos);
        }
    }

    auto ldg_chunk = [&](float* v0, float* v1, int cc) {
        #pragma unroll
        for (int j = 0; j < 7; ++j)
            if (j < 6 || tid < (NPAIR - 6 * NTHR)) {
                uint32_t o = off[j];
                const float* sp = (o & 0x80000000u) ? momF : baseF;
                const float* p  = sp + (o & 0x7FFFFFFFu) + cc * 784;
                v0[j] = __ldg(p); v1[j] = __ldg(p + 49);
            }
    };
    auto sts_chunk = [&](const float* v0, const float* v1, int bw) {
        uint32_t* dbuf = smw + bw * BUFW;
        #pragma unroll
        for (int j = 0; j < 7; ++j)
            if (j < 6 || tid < (NPAIR - 6 * NTHR)) {
                uint32_t hi = f16pack(v0[j], v1[j]);
                dbuf[dst[j]] = hi;
                if (!(off[j] & 0x80000000u)) {   // A side: also store lo residual
                    float h0, h1;
                    f16unpack(hi, h0, h1);
                    dbuf[dst[j] + 576] = f16pack(v0[j] - h0, v1[j] - h1);
                }
                accn[j] = fmaf(v0[j], v0[j], fmaf(v1[j], v1[j], accn[j]));
            }
    };

    // ---- MMA state (round-8 proven m16 layout) ----
    const int bb = wid >> 2;
    const int mr = (wid & 3) * 16 + gq;
    float acc[7][4];
    #pragma unroll
    for (int nt = 0; nt < 7; ++nt)
        #pragma unroll
        for (int u = 0; u < 4; ++u) acc[nt][u] = 0.f;

    auto mma_chunk = [&](int bw) {
        const uint32_t* W  = smw + bw * BUFW + bb * BBLK;
        const uint32_t* Bh = W + 1152;
        uint32_t ah[4], al[4];
        ah[0] = W[tg * 72 + mr];
        ah[1] = W[tg * 72 + mr + 8];
        ah[2] = W[(tg + 4) * 72 + mr];
        ah[3] = W[(tg + 4) * 72 + mr + 8];
        al[0] = W[576 + tg * 72 + mr];
        al[1] = W[576 + tg * 72 + mr + 8];
        al[2] = W[576 + (tg + 4) * 72 + mr];
        al[3] = W[576 + (tg + 4) * 72 + mr + 8];
        #pragma unroll
        for (int nt = 0; nt < 7; ++nt) {
            int o = tg * 56 + nt * 8 + gq;
            uint32_t bh0 = Bh[o];
            uint32_t bh1 = Bh[o + 224];
            mma16f(acc[nt], ah, bh0, bh1);   // hi_a * hi_b
            mma16f(acc[nt], al, bh0, bh1);   // lo_a * hi_b
        }
    };

    // ---- prologue: chunk 0 staged, chunks 1,2 prefetched (two register sets) ----
    float va0[7], va1[7], vb0[7], vb1[7];
    ldg_chunk(va0, va1, 0);
    sts_chunk(va0, va1, 0);
    ldg_chunk(vb0, vb1, 1);

    // ---- main loop: two chunks per iteration (prefetch distance 2) ----
    for (int c = 0; c < NCHUNK; c += 2) {
        __syncthreads();                       // buf0 (chunk c) ready
        if (c + 2 < NCHUNK) ldg_chunk(va0, va1, c + 2);
        mma_chunk(0);
        sts_chunk(vb0, vb1, 1);                // chunk c+1 -> buf1

        __syncthreads();                       // buf1 (chunk c+1) ready
        if (c + 3 < NCHUNK) ldg_chunk(vb0, vb1, c + 3);
        mma_chunk(1);
        if (c + 2 < NCHUNK) sts_chunk(va0, va1, 0);   // chunk c+2 -> buf0
    }

    // ---- flush norm partials ----
    #pragma unroll
    for (int j = 0; j < 7; ++j) {
        int e = tid + j * NTHR;
        if (e < NPAIR) {
            int bbx = e / 784;
            int r   = e - bbx * 784;
            int t   = r / 392;
            int pos = (r - t * 392) % 49;
            atomicAdd(&sm[SN_OFF + (bbx * 2 + t) * 64 + pos], accn[j]);
        }
    }
    __syncthreads();
    sm[SN_OFF + tid] = rsqrtf(sm[SN_OFF + tid]);
    __syncthreads();

    // ---- epilogue: mask + norms + reduce ----
    {
        const float* invP = sm + SN_OFF + (bb * 2 + 0) * 64;  // base norms
        const float* invQ = sm + SN_OFF + (bb * 2 + 1) * 64;  // moment norms
        const float* wm   = sm + WM_OFF;
        const int r0 = mr;
        const int r1 = r0 + 8;
        const int c0 = tg * 2;
        const bool u0 = r0 < HW, u1 = r1 < HW;
        const float ip0 = u0 ? invP[r0] : 0.f;
        const float ip1 = u1 ? invP[r1] : 0.f;
        float part = 0.f;
        #pragma unroll
        for (int nt = 0; nt < 7; ++nt) {
            int q0 = nt * 8 + c0;
            int q1 = q0 + 1;
            if (q0 < HW) {
                float iq = invQ[q0];
                if (u0) part = fmaf(acc[nt][0], wm[r0 * HW + q0] * ip0 * iq, part);
                if (u1) part = fmaf(acc[nt][2], wm[r1 * HW + q0] * ip1 * iq, part);
            }
            if (q1 < HW) {
                float iq = invQ[q1];
                if (u0) part = fmaf(acc[nt][1], wm[r0 * HW + q1] * ip0 * iq, part);
                if (u1) part = fmaf(acc[nt][3], wm[r1 * HW + q1] * ip1 * iq, part);
            }
        }
        #pragma unroll
        for (int o = 16; o; o >>= 1) part += __shfl_xor_sync(0xFFFFFFFFu, part, o);
        if (lane == 0) wsum[wid] = part;
    }
    __syncthreads();
    if (tid < NB) {
        float t = wsum[tid * 4] + wsum[tid * 4 + 1]
                + wsum[tid * 4 + 2] + wsum[tid * 4 + 3];
        out[b0 + tid] = -t * (1.0f / 2401.0f);
    }
}

extern "C" void kernel_launch(void* const* d_in, const int* in_sizes, int n_in,
                              void* d_out, int out_size) {
    const float* baseF = (const float*)d_in[0];
    const float* momF  = (const float*)d_in[1];
    const int*   baseA = (const int*)d_in[2];
    const int*   momA  = (const int*)d_in[3];
    float* out = (float*)d_out;
    (void)in_sizes; (void)n_in; (void)out_size;

    const int dynBytes = DYN_WORDS * 4;
    cudaFuncSetAttribute(pixpro_f16, cudaFuncAttributeMaxDynamicSharedMemorySize, dynBytes);
    pixpro_f16<<<GRID, NTHR, dynBytes>>>(baseF, momF, baseA, momA, out);
}